// round 15
// baseline (speedup 1.0000x reference)
#include <cuda_runtime.h>

#define TPB 256
#define NANN 32
#define NC 80
#define C4N 20       // float4 per anchor
#define MAXB 16

__device__ float g_acc[MAXB * 3];        // per image: cls_sum, reg_sum, num_pos
__device__ unsigned int g_count = 0;     // CTA completion counter (self-resetting)
__device__ unsigned int g_unit  = 0;     // work-unit cursor (self-resetting)

__device__ __forceinline__ float fsqrt_approx(float x) {
    float r; asm("sqrt.approx.f32 %0, %1;" : "=f"(r) : "f"(x)); return r;
}
__device__ __forceinline__ float flg2_approx(float x) {
    float r; asm("lg2.approx.f32 %0, %1;" : "=f"(r) : "f"(x)); return r;
}

#define LN2F 0.6931471805599453f
#define COEF_NEG (-0.75f * LN2F)    // term = COEF * sqrt(p) * lg2(1-p)
#define COEF_POS (-0.25f * LN2F)

__global__ __launch_bounds__(TPB, 6) void focal_persistent_kernel(
    const float* __restrict__ cls,     // [B,K,C]
    const float* __restrict__ regs,    // [B,K,4]
    const float* __restrict__ anc,     // [1,K,4]
    const float* __restrict__ ann,     // [B,NANN,5]
    float* __restrict__ out,
    int K, int B)
{
    const int tid  = threadIdx.x;
    const int lane = tid & 31;

    __shared__ float4 s_box [MAXB * NANN];
    __shared__ float  s_area[MAXB * NANN];
    __shared__ float  s_lbl [MAXB * NANN];

    for (int idx = tid; idx < B * NANN; idx += TPB) {
        const float* a = ann + (size_t)idx * 5;
        float x1 = a[0], y1 = a[1], x2 = a[2], y2 = a[3];
        s_box[idx]  = make_float4(x1, y1, x2, y2);
        s_area[idx] = (x2 - x1) * (y2 - y1);
        s_lbl[idx]  = a[4];
    }
    __syncthreads();   // the ONLY block barrier before the finalize

    const int      upi   = (K + 31) >> 5;               // warp-units per image
    const unsigned total = (unsigned)(B * upi);
    const int      quad  = lane >> 2;                   // 0..7
    const int      qlan  = lane & 3;                    // 0..3

    #define TERM(acc, pv)                                                    \
        {                                                                    \
            const float q_ = fmaf((pv), -1.0f, 1.0f);   /* FFMA-imm */       \
            acc = fmaf(fsqrt_approx(pv), flg2_approx(q_), acc);              \
        }

    while (true) {
        // ---- dynamic unit steal (one atomic per warp-unit) ----
        unsigned u = 0;
        if (lane == 0) u = atomicAdd(&g_unit, 1u);
        u = __shfl_sync(0xffffffffu, u, 0);
        if (u >= total) break;

        const int bimg  = (int)(u / (unsigned)upi);
        const int wbase = (int)(u - (unsigned)bimg * upi) << 5;
        const int k     = wbase + lane;
        const float4* s_b = (const float4*)&s_box[bimg * NANN];
        const float*  s_a = &s_area[bimg * NANN];

        // ---------------- phase 1: IoU match (round-11 form, frozen) --------
        float reg_sum = 0.0f, npos = 0.0f, corr = 0.0f, wgt = 0.0f;

        if (k < K) {
            const float4 av = *(const float4*)(anc + 4*(size_t)k);
            const float ax1 = av.x, ay1 = av.y, ax2 = av.z, ay2 = av.w;
            const float area_a = (ax2 - ax1) * (ay2 - ay1);

            float best_in = -1.0f, best_un = 1.0f;
            int   bi = 0;
            #pragma unroll 8
            for (int n = 0; n < NANN; n++) {
                const float4 bb = s_b[n];
                float iw = fmaxf(fminf(ax2, bb.z) - fmaxf(ax1, bb.x), 0.0f);
                float ih = fmaxf(fminf(ay2, bb.w) - fmaxf(ay1, bb.y), 0.0f);
                float inter = iw * ih;
                float uni   = area_a + s_a[n] - inter;
                if (inter * best_un > best_in * uni) {   // strict > == first-argmax
                    best_in = inter; best_un = uni; bi = n;
                }
            }

            const bool pos = (best_in >= 0.5f * best_un);
            const bool neg = (best_in <  0.4f * best_un);
            wgt = (pos || neg) ? COEF_NEG : 0.0f;

            if (pos) {
                npos = 1.0f;
                const int state = (int)s_lbl[bimg * NANN + bi];
                const float4 gb = s_b[bi];
                const float aw  = ax2 - ax1, ah = ay2 - ay1;
                const float acx = ax1 + 0.5f * aw, acy = ay1 + 0.5f * ah;
                const float gw  = fmaxf(gb.z - gb.x, 1.0f);
                const float gh  = fmaxf(gb.w - gb.y, 1.0f);
                const float gcx = gb.x + 0.5f * gw, gcy = gb.y + 0.5f * gh;
                float t0 = (gcx - acx) / aw * 10.0f;
                float t1 = (gcy - acy) / ah * 10.0f;
                float t2 = __logf(gw / aw) * 5.0f;
                float t3 = __logf(gh / ah) * 5.0f;
                const float4 r = *(const float4*)(regs + ((size_t)bimg * K + k) * 4);
                float d0 = fabsf(t0 - r.x), d1 = fabsf(t1 - r.y);
                float d2 = fabsf(t2 - r.z), d3 = fabsf(t3 - r.w);
                const float th = 1.0f / 9.0f, off = 0.5f / 9.0f;
                reg_sum += (d0 <= th) ? 4.5f * d0 * d0 : d0 - off;
                reg_sum += (d1 <= th) ? 4.5f * d1 * d1 : d1 - off;
                reg_sum += (d2 <= th) ? 4.5f * d2 * d2 : d2 - off;
                reg_sum += (d3 <= th) ? 4.5f * d3 * d3 : d3 - off;

                const float pc = cls[((size_t)bimg * K + k) * NC + state];
                corr = COEF_POS * fsqrt_approx(1.0f - pc) * flg2_approx(pc)
                     - COEF_NEG * fsqrt_approx(pc) * flg2_approx(1.0f - pc);
            }
        }

        // ---------------- phase 2: anchor-aligned sweep (round-11 form) -----
        float cls_sum = corr;
        if (wbase + 32 <= K) {
            const float4* p = (const float4*)cls + (size_t)bimg * K * C4N
                            + (size_t)(wbase + quad) * C4N + qlan;
            #pragma unroll
            for (int o = 0; o < 4; o++) {
                const float w = __shfl_sync(0xffffffffu, wgt, o * 8 + quad);
                float b0 = 0.0f, b1 = 0.0f, b2 = 0.0f, b3 = 0.0f;
                #pragma unroll
                for (int it = 0; it < 5; it++) {
                    const float4 v = p[o * 160 + it * 4];   // immediate offsets
                    TERM(b0, v.x);
                    TERM(b1, v.y);
                    TERM(b2, v.z);
                    TERM(b3, v.w);
                }
                cls_sum = fmaf(w, (b0 + b1) + (b2 + b3), cls_sum);
            }
        } else if (wbase < K) {
            // partial unit (K % 32 != 0 only): masked per-element fallback
            const float4* p = (const float4*)cls + (size_t)bimg * K * C4N
                            + (size_t)wbase * C4N + lane;
            const int rmax = (K - wbase) * C4N - 1 - lane;
            for (int it = 0; it < C4N; it++) {
                const int   a_loc = (it * 32 + lane) / 20;
                const float w     = __shfl_sync(0xffffffffu, wgt, a_loc);
                const float4 v    = p[max(min(it * 32, rmax), 0)];
                float t0 = 0.f, t1 = 0.f, t2 = 0.f, t3 = 0.f;
                TERM(t0, v.x); TERM(t1, v.y); TERM(t2, v.z); TERM(t3, v.w);
                cls_sum = fmaf(w, (t0 + t1) + (t2 + t3), cls_sum);
            }
        }

        // ---- per-unit warp reduce + image accumulators ----
        #pragma unroll
        for (int o = 16; o > 0; o >>= 1) {
            cls_sum += __shfl_down_sync(0xffffffffu, cls_sum, o);
            reg_sum += __shfl_down_sync(0xffffffffu, reg_sum, o);
            npos    += __shfl_down_sync(0xffffffffu, npos, o);
        }
        if (lane == 0) {
            atomicAdd(&g_acc[bimg*3+0], cls_sum);
            atomicAdd(&g_acc[bimg*3+1], reg_sum);
            atomicAdd(&g_acc[bimg*3+2], npos);
        }
    }
    #undef TERM

    // ---------------- finalize (last CTA) -------------------------------------
    __syncthreads();
    if (tid == 0) {
        __threadfence();
        const unsigned int old = atomicAdd(&g_count, 1u);
        if (old == gridDim.x - 1u) {
            float cs = 0.0f, rs = 0.0f;
            for (int bb = 0; bb < B; bb++) {
                const float acc_c = atomicAdd(&g_acc[bb*3+0], 0.0f);
                const float acc_r = atomicAdd(&g_acc[bb*3+1], 0.0f);
                const float np    = atomicAdd(&g_acc[bb*3+2], 0.0f);
                cs += acc_c / fmaxf(np, 1.0f);
                rs += (np > 0.0f) ? acc_r / fmaxf(np * 4.0f, 1.0f) : 0.0f;
            }
            out[0] = cs / (float)B;
            out[1] = rs / (float)B;
            for (int i = 0; i < B * 3; i++) g_acc[i] = 0.0f;
            g_unit = 0u;
            __threadfence();
            g_count = 0u;
            __threadfence();
        }
    }
}

extern "C" void kernel_launch(void* const* d_in, const int* in_sizes, int n_in,
                              void* d_out, int out_size) {
    const float* cls  = (const float*)d_in[0];   // [B,K,C]
    const float* regs = (const float*)d_in[1];   // [B,K,4]
    const float* anc  = (const float*)d_in[2];   // [1,K,4]
    const float* ann  = (const float*)d_in[3];   // [B,NANN,5]

    const int K = in_sizes[2] / 4;
    const int B = in_sizes[3] / (NANN * 5);

    int nsm = 148;
    cudaDeviceGetAttribute(&nsm, cudaDevAttrMultiProcessorCount, 0);

    focal_persistent_kernel<<<nsm * 6, TPB>>>(cls, regs, anc, ann,
                                              (float*)d_out, K, B);
}

// round 16
// speedup vs baseline: 2.0631x; 2.0631x over previous
#include <cuda_runtime.h>

#define TPB 256      // 8 warps; each warp owns 32 anchors per tile
#define NANN 32
#define NC 80
#define C4N 20       // float4 per anchor
#define MAXB 16
#define GRIDX 111    // 111 * 8 images = 888 CTAs = 148 SMs * 6 (one wave)

__device__ float g_acc[MAXB * 3];        // per image: cls_sum, reg_sum, num_pos
__device__ unsigned int g_count = 0;     // completed-CTA counter (self-resetting)

__device__ __forceinline__ float fsqrt_approx(float x) {
    float r; asm("sqrt.approx.f32 %0, %1;" : "=f"(r) : "f"(x)); return r;
}
__device__ __forceinline__ float flg2_approx(float x) {
    float r; asm("lg2.approx.f32 %0, %1;" : "=f"(r) : "f"(x)); return r;
}

#define LN2F 0.6931471805599453f
#define COEF_NEG (-0.75f * LN2F)    // term = COEF * sqrt(p) * lg2(1-p)
#define COEF_POS (-0.25f * LN2F)

__global__ __launch_bounds__(TPB, 6) void focal_fused_kernel(
    const float* __restrict__ cls,     // [B,K,C]
    const float* __restrict__ regs,    // [B,K,4]
    const float* __restrict__ anc,     // [1,K,4]
    const float* __restrict__ ann,     // [B,NANN,5]
    float* __restrict__ out,
    int K, int B)
{
    const int b    = blockIdx.y;
    const int tid  = threadIdx.x;
    const int wid  = tid >> 5;
    const int lane = tid & 31;

    __shared__ float4 s_box[NANN];
    __shared__ float  s_area[NANN];
    __shared__ float  s_lbl[NANN];
    __shared__ float  s_red[3][TPB / 32];

    if (tid < NANN) {
        const float* a = ann + (size_t)b * NANN * 5 + tid * 5;
        float x1 = a[0], y1 = a[1], x2 = a[2], y2 = a[3];
        s_box[tid]  = make_float4(x1, y1, x2, y2);
        s_area[tid] = (x2 - x1) * (y2 - y1);
        s_lbl[tid]  = a[4];
    }
    __syncthreads();   // the ONLY block barrier before the final reduce

    const int quad = lane >> 2;      // 0..7 : anchor within group
    const int qlan = lane & 3;       // 0..3 : f4 slot within anchor
    const int tiles = (K + TPB - 1) / TPB;

    float cls_acc = 0.0f, reg_acc = 0.0f, npos_acc = 0.0f;

    #define TERM(acc, pv)                                                    \
        {                                                                    \
            const float q_ = fmaf((pv), -1.0f, 1.0f);   /* FFMA-imm */       \
            acc = fmaf(fsqrt_approx(pv), flg2_approx(q_), acc);              \
        }

    // ---- persistent tile loop: no barrier inside -> warps drift, phase-1
    //      compute of one warp overlaps sweep DRAM drain of another ----------
    for (int t = blockIdx.x; t < tiles; t += GRIDX) {
        const int s    = t * TPB;
        const int base = s + (wid << 5);     // this warp's first anchor
        const int k    = base + lane;

        // ------------- phase 1: IoU match (round-11 form, frozen) ----------
        float reg_sum = 0.0f, npos = 0.0f, corr = 0.0f, wgt = 0.0f;

        if (k < K) {
            const float4 av = *(const float4*)(anc + 4*(size_t)k);
            const float ax1 = av.x, ay1 = av.y, ax2 = av.z, ay2 = av.w;
            const float area_a = (ax2 - ax1) * (ay2 - ay1);

            float best_in = -1.0f, best_un = 1.0f;
            int   bi = 0;
            #pragma unroll 8
            for (int n = 0; n < NANN; n++) {
                const float4 bb = s_box[n];
                float iw = fmaxf(fminf(ax2, bb.z) - fmaxf(ax1, bb.x), 0.0f);
                float ih = fmaxf(fminf(ay2, bb.w) - fmaxf(ay1, bb.y), 0.0f);
                float inter = iw * ih;
                float uni   = area_a + s_area[n] - inter;
                if (inter * best_un > best_in * uni) {   // strict > == first-argmax
                    best_in = inter; best_un = uni; bi = n;
                }
            }

            const bool pos = (best_in >= 0.5f * best_un);
            const bool neg = (best_in <  0.4f * best_un);
            wgt = (pos || neg) ? COEF_NEG : 0.0f;

            if (pos) {
                npos = 1.0f;
                const int state = (int)s_lbl[bi];
                const float4 gb = s_box[bi];
                const float aw  = ax2 - ax1, ah = ay2 - ay1;
                const float acx = ax1 + 0.5f * aw, acy = ay1 + 0.5f * ah;
                const float gw  = fmaxf(gb.z - gb.x, 1.0f);
                const float gh  = fmaxf(gb.w - gb.y, 1.0f);
                const float gcx = gb.x + 0.5f * gw, gcy = gb.y + 0.5f * gh;
                float t0 = (gcx - acx) / aw * 10.0f;
                float t1 = (gcy - acy) / ah * 10.0f;
                float t2 = __logf(gw / aw) * 5.0f;
                float t3 = __logf(gh / ah) * 5.0f;
                const float4 r = *(const float4*)(regs + ((size_t)b * K + k) * 4);
                float d0 = fabsf(t0 - r.x), d1 = fabsf(t1 - r.y);
                float d2 = fabsf(t2 - r.z), d3 = fabsf(t3 - r.w);
                const float th = 1.0f / 9.0f, off = 0.5f / 9.0f;
                reg_sum += (d0 <= th) ? 4.5f * d0 * d0 : d0 - off;
                reg_sum += (d1 <= th) ? 4.5f * d1 * d1 : d1 - off;
                reg_sum += (d2 <= th) ? 4.5f * d2 * d2 : d2 - off;
                reg_sum += (d3 <= th) ? 4.5f * d3 * d3 : d3 - off;

                const float pc = cls[((size_t)b * K + k) * NC + state];
                corr = COEF_POS * fsqrt_approx(1.0f - pc) * flg2_approx(pc)
                     - COEF_NEG * fsqrt_approx(pc) * flg2_approx(1.0f - pc);
            }
        }

        // ------------- phase 2: anchor-aligned sweep (round-11 form) -------
        float cls_sum = corr;
        if (base + 32 <= K) {
            const float4* p = (const float4*)cls + (size_t)b * K * C4N
                            + (size_t)(base + quad) * C4N + qlan;
            #pragma unroll
            for (int o = 0; o < 4; o++) {
                const float w = __shfl_sync(0xffffffffu, wgt, o * 8 + quad);
                float b0 = 0.0f, b1 = 0.0f, b2 = 0.0f, b3 = 0.0f;
                #pragma unroll
                for (int it = 0; it < 5; it++) {
                    const float4 v = p[o * 160 + it * 4];   // immediate offsets
                    TERM(b0, v.x);
                    TERM(b1, v.y);
                    TERM(b2, v.z);
                    TERM(b3, v.w);
                }
                cls_sum = fmaf(w, (b0 + b1) + (b2 + b3), cls_sum);
            }
        } else if (base < K) {
            // partial warp (K % 32 != 0 only): masked per-element fallback
            const float4* p = (const float4*)cls + (size_t)b * K * C4N
                            + (size_t)base * C4N + lane;
            const int rmax = (K - base) * C4N - 1 - lane;
            for (int it = 0; it < C4N; it++) {
                const int   a_loc = (it * 32 + lane) / 20;
                const float w     = __shfl_sync(0xffffffffu, wgt, a_loc);
                const float4 v    = p[max(min(it * 32, rmax), 0)];
                float t0 = 0.f, t1 = 0.f, t2 = 0.f, t3 = 0.f;
                TERM(t0, v.x); TERM(t1, v.y); TERM(t2, v.z); TERM(t3, v.w);
                cls_sum = fmaf(w, (t0 + t1) + (t2 + t3), cls_sum);
            }
        }

        cls_acc  += cls_sum;
        reg_acc  += reg_sum;
        npos_acc += npos;
    }
    #undef TERM

    // ---------------- one block reduction + finalize at the very end ---------
    #pragma unroll
    for (int o = 16; o > 0; o >>= 1) {
        cls_acc  += __shfl_down_sync(0xffffffffu, cls_acc, o);
        reg_acc  += __shfl_down_sync(0xffffffffu, reg_acc, o);
        npos_acc += __shfl_down_sync(0xffffffffu, npos_acc, o);
    }
    if (lane == 0) { s_red[0][wid] = cls_acc; s_red[1][wid] = reg_acc; s_red[2][wid] = npos_acc; }
    __syncthreads();

    if (tid == 0) {
        float c = 0.0f, r = 0.0f, n = 0.0f;
        #pragma unroll
        for (int i = 0; i < TPB / 32; i++) { c += s_red[0][i]; r += s_red[1][i]; n += s_red[2][i]; }
        atomicAdd(&g_acc[b*3+0], c);
        atomicAdd(&g_acc[b*3+1], r);
        atomicAdd(&g_acc[b*3+2], n);
        __threadfence();

        const unsigned int total = gridDim.x * gridDim.y;
        const unsigned int old = atomicAdd(&g_count, 1u);
        if (old == total - 1u) {
            float cs = 0.0f, rs = 0.0f;
            for (int bb = 0; bb < B; bb++) {
                const float acc_c = atomicAdd(&g_acc[bb*3+0], 0.0f);
                const float acc_r = atomicAdd(&g_acc[bb*3+1], 0.0f);
                const float np    = atomicAdd(&g_acc[bb*3+2], 0.0f);
                cs += acc_c / fmaxf(np, 1.0f);
                rs += (np > 0.0f) ? acc_r / fmaxf(np * 4.0f, 1.0f) : 0.0f;
            }
            out[0] = cs / (float)B;
            out[1] = rs / (float)B;
            for (int i = 0; i < B * 3; i++) g_acc[i] = 0.0f;
            __threadfence();
            g_count = 0u;
            __threadfence();
        }
    }
}

extern "C" void kernel_launch(void* const* d_in, const int* in_sizes, int n_in,
                              void* d_out, int out_size) {
    const float* cls  = (const float*)d_in[0];   // [B,K,C]
    const float* regs = (const float*)d_in[1];   // [B,K,4]
    const float* anc  = (const float*)d_in[2];   // [1,K,4]
    const float* ann  = (const float*)d_in[3];   // [B,NANN,5]

    const int K = in_sizes[2] / 4;
    const int B = in_sizes[3] / (NANN * 5);

    dim3 grid(GRIDX, B);
    focal_fused_kernel<<<grid, TPB>>>(cls, regs, anc, ann, (float*)d_out, K, B);
}

// round 17
// speedup vs baseline: 2.4185x; 1.1723x over previous
#include <cuda_runtime.h>

#define TPB 256      // 8 warps; each warp owns 32 anchors
#define NANN 32
#define NC 80
#define C4N 20       // float4 per anchor
#define MAXB 16

__device__ float g_acc[MAXB * 3];        // per image: cls_sum, reg_sum, num_pos
__device__ unsigned int g_count = 0;     // completed-block counter (self-resetting)

__device__ __forceinline__ float fsqrt_approx(float x) {
    float r; asm("sqrt.approx.f32 %0, %1;" : "=f"(r) : "f"(x)); return r;
}
__device__ __forceinline__ float flg2_approx(float x) {
    float r; asm("lg2.approx.f32 %0, %1;" : "=f"(r) : "f"(x)); return r;
}
// evict-first streaming float4 load (single-use data: don't hold L2 lines)
__device__ __forceinline__ float4 ldcs4(const float4* p) {
    float4 v;
    asm("ld.global.cs.v4.f32 {%0, %1, %2, %3}, [%4];"
        : "=f"(v.x), "=f"(v.y), "=f"(v.z), "=f"(v.w) : "l"(p));
    return v;
}

#define LN2F 0.6931471805599453f
#define COEF_NEG (-0.75f * LN2F)    // term = COEF * sqrt(p) * lg2(1-p)
#define COEF_POS (-0.25f * LN2F)

__global__ __launch_bounds__(TPB, 6) void focal_fused_kernel(
    const float* __restrict__ cls,     // [B,K,C]
    const float* __restrict__ regs,    // [B,K,4]
    const float* __restrict__ anc,     // [1,K,4]
    const float* __restrict__ ann,     // [B,NANN,5]
    float* __restrict__ out,
    int K, int B)
{
    const int b    = blockIdx.y;
    const int s    = blockIdx.x * TPB;
    const int tid  = threadIdx.x;
    const int wid  = tid >> 5;
    const int lane = tid & 31;

    __shared__ float4 s_box[NANN];
    __shared__ float  s_area[NANN];
    __shared__ float  s_lbl[NANN];
    __shared__ float  s_red[3][TPB / 32];

    if (tid < NANN) {
        const float* a = ann + (size_t)b * NANN * 5 + tid * 5;
        float x1 = a[0], y1 = a[1], x2 = a[2], y2 = a[3];
        s_box[tid]  = make_float4(x1, y1, x2, y2);
        s_area[tid] = (x2 - x1) * (y2 - y1);
        s_lbl[tid]  = a[4];
    }
    __syncthreads();   // the ONLY block barrier before heavy work

    const int base = s + (wid << 5);     // this warp's first anchor
    const int k    = base + lane;

    // ---------------- phase 1: IoU match (round-11 form, frozen) ------------
    float reg_sum = 0.0f, npos = 0.0f, corr = 0.0f, wgt = 0.0f;

    if (k < K) {
        const float4 av = __ldg((const float4*)(anc + 4*(size_t)k));
        const float ax1 = av.x, ay1 = av.y, ax2 = av.z, ay2 = av.w;
        const float area_a = (ax2 - ax1) * (ay2 - ay1);

        float best_in = -1.0f, best_un = 1.0f;
        int   bi = 0;
        #pragma unroll 8
        for (int n = 0; n < NANN; n++) {
            const float4 bb = s_box[n];
            float iw = fmaxf(fminf(ax2, bb.z) - fmaxf(ax1, bb.x), 0.0f);
            float ih = fmaxf(fminf(ay2, bb.w) - fmaxf(ay1, bb.y), 0.0f);
            float inter = iw * ih;
            float uni   = area_a + s_area[n] - inter;   // always >= 256 here
            if (inter * best_un > best_in * uni) {      // strict > == first-argmax
                best_in = inter; best_un = uni; bi = n;
            }
        }

        const bool pos = (best_in >= 0.5f * best_un);
        const bool neg = (best_in <  0.4f * best_un);
        wgt = (pos || neg) ? COEF_NEG : 0.0f;

        if (pos) {
            npos = 1.0f;
            const int state = (int)s_lbl[bi];
            const float4 gb = s_box[bi];
            const float aw  = ax2 - ax1, ah = ay2 - ay1;
            const float acx = ax1 + 0.5f * aw, acy = ay1 + 0.5f * ah;
            const float gw  = fmaxf(gb.z - gb.x, 1.0f);
            const float gh  = fmaxf(gb.w - gb.y, 1.0f);
            const float gcx = gb.x + 0.5f * gw, gcy = gb.y + 0.5f * gh;
            float t0 = (gcx - acx) / aw * 10.0f;
            float t1 = (gcy - acy) / ah * 10.0f;
            float t2 = __logf(gw / aw) * 5.0f;
            float t3 = __logf(gh / ah) * 5.0f;
            const float4 r = *(const float4*)(regs + ((size_t)b * K + k) * 4);
            float d0 = fabsf(t0 - r.x), d1 = fabsf(t1 - r.y);
            float d2 = fabsf(t2 - r.z), d3 = fabsf(t3 - r.w);
            const float th = 1.0f / 9.0f, off = 0.5f / 9.0f;
            reg_sum += (d0 <= th) ? 4.5f * d0 * d0 : d0 - off;
            reg_sum += (d1 <= th) ? 4.5f * d1 * d1 : d1 - off;
            reg_sum += (d2 <= th) ? 4.5f * d2 * d2 : d2 - off;
            reg_sum += (d3 <= th) ? 4.5f * d3 * d3 : d3 - off;

            // swap negative-formula term for positive-formula term (matched class)
            const float pc = __ldcs(&cls[((size_t)b * K + k) * NC + state]);
            corr = COEF_POS * fsqrt_approx(1.0f - pc) * flg2_approx(pc)
                 - COEF_NEG * fsqrt_approx(pc) * flg2_approx(1.0f - pc);
        }
    }

    // ---------------- phase 2: anchor-aligned sweep (round-11 form) ----------
    // evict-first streaming loads: 256MB single-use stream must not thrash L2.
    float cls_sum = corr;
    const int quad = lane >> 2;      // 0..7 : anchor within group
    const int qlan = lane & 3;       // 0..3 : f4 slot within anchor

    #define TERM(acc, pv)                                                    \
        {                                                                    \
            const float q_ = fmaf((pv), -1.0f, 1.0f);   /* FFMA-imm */       \
            acc = fmaf(fsqrt_approx(pv), flg2_approx(q_), acc);              \
        }

    if (base + 32 <= K) {
        const float4* p = (const float4*)cls + (size_t)b * K * C4N
                        + (size_t)(base + quad) * C4N + qlan;
        #pragma unroll
        for (int o = 0; o < 4; o++) {
            const float w = __shfl_sync(0xffffffffu, wgt, o * 8 + quad);
            float b0 = 0.0f, b1 = 0.0f, b2 = 0.0f, b3 = 0.0f;
            #pragma unroll
            for (int it = 0; it < 5; it++) {
                const float4 v = ldcs4(p + o * 160 + it * 4);  // immediate offsets
                TERM(b0, v.x);
                TERM(b1, v.y);
                TERM(b2, v.z);
                TERM(b3, v.w);
            }
            cls_sum = fmaf(w, (b0 + b1) + (b2 + b3), cls_sum);
        }
    } else if (base < K) {
        // partial warp (K % 32 != 0 only): masked per-element fallback
        const float4* p = (const float4*)cls + (size_t)b * K * C4N
                        + (size_t)base * C4N + lane;
        const int rmax = (K - base) * C4N - 1 - lane;
        for (int it = 0; it < C4N; it++) {
            const int   a_loc = (it * 32 + lane) / 20;
            const float w     = __shfl_sync(0xffffffffu, wgt, a_loc);
            const float4 v    = ldcs4(p + max(min(it * 32, rmax), 0));
            float t0 = 0.f, t1 = 0.f, t2 = 0.f, t3 = 0.f;
            TERM(t0, v.x); TERM(t1, v.y); TERM(t2, v.z); TERM(t3, v.w);
            cls_sum = fmaf(w, (t0 + t1) + (t2 + t3), cls_sum);
        }
    }
    #undef TERM

    // ---------------- block reduction + finalize ------------------------------
    #pragma unroll
    for (int o = 16; o > 0; o >>= 1) {
        cls_sum += __shfl_down_sync(0xffffffffu, cls_sum, o);
        reg_sum += __shfl_down_sync(0xffffffffu, reg_sum, o);
        npos    += __shfl_down_sync(0xffffffffu, npos, o);
    }
    if (lane == 0) { s_red[0][wid] = cls_sum; s_red[1][wid] = reg_sum; s_red[2][wid] = npos; }
    __syncthreads();

    if (tid == 0) {
        float c = 0.0f, r = 0.0f, n = 0.0f;
        #pragma unroll
        for (int i = 0; i < TPB / 32; i++) { c += s_red[0][i]; r += s_red[1][i]; n += s_red[2][i]; }
        atomicAdd(&g_acc[b*3+0], c);
        atomicAdd(&g_acc[b*3+1], r);
        atomicAdd(&g_acc[b*3+2], n);
        __threadfence();

        const unsigned int total = gridDim.x * gridDim.y;
        const unsigned int old = atomicAdd(&g_count, 1u);
        if (old == total - 1u) {
            float cs = 0.0f, rs = 0.0f;
            for (int bb = 0; bb < B; bb++) {
                const float acc_c = atomicAdd(&g_acc[bb*3+0], 0.0f);
                const float acc_r = atomicAdd(&g_acc[bb*3+1], 0.0f);
                const float np    = atomicAdd(&g_acc[bb*3+2], 0.0f);
                cs += acc_c / fmaxf(np, 1.0f);
                rs += (np > 0.0f) ? acc_r / fmaxf(np * 4.0f, 1.0f) : 0.0f;
            }
            out[0] = cs / (float)B;
            out[1] = rs / (float)B;
            for (int i = 0; i < B * 3; i++) g_acc[i] = 0.0f;
            __threadfence();
            g_count = 0u;
            __threadfence();
        }
    }
}

extern "C" void kernel_launch(void* const* d_in, const int* in_sizes, int n_in,
                              void* d_out, int out_size) {
    const float* cls  = (const float*)d_in[0];   // [B,K,C]
    const float* regs = (const float*)d_in[1];   // [B,K,4]
    const float* anc  = (const float*)d_in[2];   // [1,K,4]
    const float* ann  = (const float*)d_in[3];   // [B,NANN,5]

    const int K = in_sizes[2] / 4;
    const int B = in_sizes[3] / (NANN * 5);

    dim3 grid((K + TPB - 1) / TPB, B);
    focal_fused_kernel<<<grid, TPB>>>(cls, regs, anc, ann, (float*)d_out, K, B);
}